// round 15
// baseline (speedup 1.0000x reference)
#include <cuda_runtime.h>
#include <cuda_fp16.h>
#include <cstdint>

// ---------------------------------------------------------------------------
// Problem constants
// ---------------------------------------------------------------------------
#define M_TOK   64
#define KDIM    8192
#define NOUT    14336
#define KW      (KDIM / 2)          // 4096 int32 per output row
#define NTILE   128
#define GRID_N  (NOUT / NTILE)      // 112 CTAs = one wave

// Dynamic SMEM: per warp-group 2-stage x ring (2 x 16KB) at grp*32768;
// mbarriers at 65536; first 33KB reused for split-K reduction after mainloop.
#define MBAR_OFF 65536
#define SMEM_TOTAL 65664

// x (fp16, k-permuted + bank-swizzled) staged per 64-k chunk: 128 chunks x 8KB
__device__ __align__(16) unsigned char g_ximg[(size_t)M_TOK * KDIM * 2];  // 1 MB

// ---------------------------------------------------------------------------
// Helpers
// ---------------------------------------------------------------------------
__device__ __forceinline__ uint2 lds64(uint32_t addr) {
    uint2 r;
    asm volatile("ld.shared.v2.u32 {%0,%1}, [%2];" : "=r"(r.x), "=r"(r.y) : "r"(addr));
    return r;
}
__device__ __forceinline__ void mma16816(float* d, uint32_t a0, uint32_t a1,
                                         uint32_t a2, uint32_t a3,
                                         uint32_t b0, uint32_t b1) {
    asm volatile(
        "mma.sync.aligned.m16n8k16.row.col.f32.f16.f16.f32 "
        "{%0,%1,%2,%3}, {%4,%5,%6,%7}, {%8,%9}, {%0,%1,%2,%3};"
        : "+f"(d[0]), "+f"(d[1]), "+f"(d[2]), "+f"(d[3])
        : "r"(a0), "r"(a1), "r"(a2), "r"(a3), "r"(b0), "r"(b1));
}

#define MBARRIER_INIT(addr, cnt) \
    asm volatile("mbarrier.init.shared.b64 [%0], %1;" :: "r"(addr), "r"(cnt) : "memory")
#define MBARRIER_EXPECT_TX(addr, bytes) \
    asm volatile("mbarrier.arrive.expect_tx.shared.b64 _, [%0], %1;" \
                 :: "r"(addr), "r"(bytes) : "memory")
#define FENCE_PROXY_ASYNC() \
    asm volatile("fence.proxy.async.shared::cta;" ::: "memory")
#define BULK_G2S(dst, src, bytes, mbar) \
    asm volatile("cp.async.bulk.shared::cluster.global.mbarrier::complete_tx::bytes " \
                 "[%0], [%1], %2, [%3];" \
                 :: "r"(dst), "l"(src), "r"(bytes), "r"(mbar) : "memory")
#define MBARRIER_WAIT_PARITY(addr, parity) do {                                          \
    uint32_t _m = (addr), _p = (parity), _done;                                          \
    asm volatile("{ .reg .pred p; mbarrier.try_wait.parity.acquire.cta.shared::cta.b64 " \
                 "p, [%1], %2; selp.b32 %0, 1, 0, p; }"                                  \
                 : "=r"(_done) : "r"(_m), "r"(_p) : "memory");                           \
    if (!_done) {                                                                        \
        asm volatile("{ .reg .pred P1; WL_%=: "                                          \
                     "mbarrier.try_wait.parity.acquire.cta.shared::cta.b64 P1, [%0], %1, 0x989680; " \
                     "@P1 bra.uni WD_%=; bra.uni WL_%=; WD_%=: }"                        \
                     :: "r"(_m), "r"(_p) : "memory");                                    \
    } } while (0)

// Per-warp-group barrier (256 threads): decouples the two k-split pipelines.
#define GROUP_BAR(grp_) \
    asm volatile("bar.sync %0, 256;" :: "r"((grp_) + 1) : "memory")

// int4-pair dequant: one int32 (value 0..255; lo nibble = even k) -> f16x2 {qlo,qhi}.
// lo half = 0x6408 ^ nibLo = 1032 + qlo (exact); HSUB2 by 1032 -> exact signed int4.
__device__ __forceinline__ uint32_t dq2(uint32_t v) {
    uint32_t t = (v & 0xFu) ^ 0x64086408u;
    uint32_t p = t ^ ((v << 12) & 0x000F0000u);
    __half2 hp = *reinterpret_cast<__half2*>(&p);
    __half2 r = __hsub2(hp, __half2half2(__ushort_as_half((unsigned short)0x6408)));
    return *reinterpret_cast<uint32_t*>(&r);
}

// ---------------------------------------------------------------------------
// Pre-kernel: x [64,8192] f32 -> f16 with the k-permutation + LDS swizzle baked in.
// Chunk cc covers physical k [cc*64, cc*64+64). Granule q (q = 4c+s, c=q>>2, s=q&3)
// stores 4 halves = physical k {8c+2s, 8c+2s+1, 32+8c+2s, 33+8c+2s} at byte offset
// tok*128 + ((q ^ (tok&7)) * 8) inside the 8KB chunk tile.
// ---------------------------------------------------------------------------
__global__ void convert_x(const float* __restrict__ x) {
    int tg  = blockIdx.x * 256 + threadIdx.x;    // 131072 threads
    int cc  = tg >> 10;
    int rem = tg & 1023;
    int tok = rem >> 4;
    int q   = rem & 15;
    int c = q >> 2, s = q & 3;
    int k0 = cc * 64 + 8 * c + 2 * s;
    float2 v0 = *reinterpret_cast<const float2*>(x + (size_t)tok * KDIM + k0);
    float2 v1 = *reinterpret_cast<const float2*>(x + (size_t)tok * KDIM + k0 + 32);
    __half2 h0 = __floats2half2_rn(v0.x, v0.y);
    __half2 h1 = __floats2half2_rn(v1.x, v1.y);
    uint2 st;
    st.x = *reinterpret_cast<uint32_t*>(&h0);
    st.y = *reinterpret_cast<uint32_t*>(&h1);
    *reinterpret_cast<uint2*>(g_ximg + (size_t)cc * 8192 + tok * 128 +
                              ((q ^ (tok & 7)) << 3)) = st;
}

// ---------------------------------------------------------------------------
// Main kernel: CTA = 128 out-rows x 64 tokens, 512 threads / 16 warps,
// SPLIT-K across two warp-groups (group g owns k in [g*4096, (g+1)*4096)),
// each group = the R8 engine (8 row-warps x 16 rows x 64 tokens; weights
// gmem->regs->dq2 with 2-buffer prefetch); x staged by cp.async.bulk with
// mbarrier completion. R15 changes vs R14:
//  (1) mainloop barrier is PER-GROUP (bar.sync grp+1, 256), so the two
//      k-pipelines run decoupled instead of lock-stepped on __syncthreads;
//  (2) LOADW(W1) hoisted ABOVE the mbarrier wait: its 577-cyc LDG latency
//      overlaps the x-stage wait instead of starting after it.
// ---------------------------------------------------------------------------
__global__ __launch_bounds__(512, 1)
void qmain(const int* __restrict__ wp, const float* __restrict__ ws,
           const float* __restrict__ bias, float* __restrict__ out) {
    extern __shared__ __align__(16) unsigned char smem[];

    const int tid  = threadIdx.x;
    const int lane = tid & 31, warp = tid >> 5;       // warp 0..15
    const int grp  = warp >> 3;                       // 0,1: k-split group
    const int wg   = warp & 7;                        // row-warp within group
    const int rl = lane >> 2, cl = lane & 3;
    const int tl = tid & 255;                         // thread index within group
    const int r0 = blockIdx.x * NTILE;

    const uint32_t sb = (uint32_t)__cvta_generic_to_shared(smem);
    const uint32_t ringbase = (uint32_t)grp * 32768u;
    const uint32_t mb0 = sb + MBAR_OFF + (uint32_t)grp * 32u;       // stage 0 barrier
    const uint32_t mb1 = mb0 + 16u;                                 // stage 1 barrier

    // weight row pointers [rh]; group offset grp*2048 int32 = grp*4096 k
    const int* wptr[2];
#pragma unroll
    for (int rh = 0; rh < 2; rh++)
        wptr[rh] = wp + (size_t)(r0 + wg * 16 + rh * 8 + rl) * KW +
                   grp * (KW / 2) + 4 * cl;

    // B-fragment smem addresses: token = nt*8 + rl (all 64 tokens per warp)
    uint32_t baddr[8];
#pragma unroll
    for (int nt = 0; nt < 8; nt++)
        baddr[nt] = sb + ringbase + (uint32_t)(nt * 8 + rl) * 128;
    uint32_t gq[4];
#pragma unroll
    for (int s = 0; s < 4; s++)
        gq[s] = (uint32_t)(((4 * cl + s) ^ rl) << 3);

    // LOADW: local half-chunk h (0..63) -> buffer; guarded for the tail
#define LOADW(W, h_) do {                                                       \
        if ((h_) < 64) {                                                        \
            _Pragma("unroll")                                                   \
            for (int rh_ = 0; rh_ < 2; rh_++) {                                 \
                const int* p_ = wptr[rh_] + (h_) * 32;                          \
                W[rh_][0] = *reinterpret_cast<const uint4*>(p_);                \
                W[rh_][1] = *reinterpret_cast<const uint4*>(p_ + 16);           \
            }                                                                   \
        } } while (0)

#define COMP4(u4, s_) ((s_) == 0 ? (u4).x : (s_) == 1 ? (u4).y : (s_) == 2 ? (u4).z : (u4).w)

#define COMPUTE(W, sx_) do {                                                    \
        _Pragma("unroll")                                                       \
        for (int s_ = 0; s_ < 4; s_++) {                                        \
            uint32_t a0 = dq2(COMP4(W[0][0], s_));                              \
            uint32_t a1 = dq2(COMP4(W[1][0], s_));                              \
            uint32_t a2 = dq2(COMP4(W[0][1], s_));                              \
            uint32_t a3 = dq2(COMP4(W[1][1], s_));                              \
            _Pragma("unroll")                                                   \
            for (int nt_ = 0; nt_ < 8; nt_++) {                                 \
                uint2 b_ = lds64(baddr[nt_] + (sx_) + gq[s_]);                  \
                mma16816(d[nt_], a0, a1, a2, a3, b_.x, b_.y);                   \
            }                                                                   \
        } } while (0)

    // x iteration j (0..31) of this group = g_ximg 16KB block (grp*32 + j)
#define ISSUE_BULK(j_, slot_) do {                                             \
        const unsigned char* xg_ = g_ximg + (size_t)(grp * 32 + (j_)) * 16384; \
        const uint32_t xd_ = sb + ringbase + (uint32_t)(slot_) * 16384u;       \
        const uint32_t mb_ = (slot_) ? mb1 : mb0;                              \
        MBARRIER_EXPECT_TX(mb_, 16384u);                                       \
        BULK_G2S(xd_, xg_, 16384u, mb_);                                       \
    } while (0)

    uint4 W0[2][2], W1[2][2];
    float d[8][4] = {};

    // Barrier init (one thread per group), then prologue bulk fills
    if (tl == 0) { MBARRIER_INIT(mb0, 1); MBARRIER_INIT(mb1, 1); }
    __syncthreads();
    if (tl == 0) {
        FENCE_PROXY_ASYNC();
        ISSUE_BULK(0, 0);
        ISSUE_BULK(1, 1);
    }

    // First weight half in registers
    LOADW(W0, 0);

    for (int j = 0; j < 32; j++) {
        // Hoisted: W1's LDGs fly during the mbarrier wait (registers are
        // thread-private; last read of W1 was this thread's own COMPUTE).
        LOADW(W1, 2 * j + 1);

        // Wait for stage (j&1) fill number (j>>1): parity = (j>>1)&1
        MBARRIER_WAIT_PARITY((j & 1) ? mb1 : mb0, (uint32_t)((j >> 1) & 1));
        const uint32_t sx = (uint32_t)(j & 1) * 16384u;

        COMPUTE(W0, sx);
        LOADW(W0, 2 * j + 2);          // next iteration's 1st half (guarded)
        COMPUTE(W1, sx + 8192u);

        GROUP_BAR(grp);                // this group done reading stage j&1
        if (tl == 0 && j + 2 < 32) ISSUE_BULK(j + 2, j & 1);
    }

    // ---- split-K reduction + epilogue ----
    // Block-wide sync: group 1's partials overwrite group 0's x-ring region,
    // so BOTH groups must be fully done with the mainloop first.
    __syncthreads();

    // sred layout: warp wg -> 16 rows x 64 tokens, row stride 65 floats (pad)
    float* sred = reinterpret_cast<float*>(smem);
    if (grp == 1) {
#pragma unroll
        for (int nt = 0; nt < 8; nt++) {
            const int T = nt * 8 + 2 * cl;
            float* b0 = sred + wg * 1040 + rl * 65 + T;
            float* b1 = sred + wg * 1040 + (rl + 8) * 65 + T;
            b0[0] = d[nt][0]; b0[1] = d[nt][1];
            b1[0] = d[nt][2]; b1[1] = d[nt][3];
        }
    }
    __syncthreads();
    if (grp == 0) {
        const int R0g = r0 + wg * 16 + rl;
        const float sc0 = ws[R0g],     bi0 = bias[R0g];
        const float sc1 = ws[R0g + 8], bi1 = bias[R0g + 8];
#pragma unroll
        for (int nt = 0; nt < 8; nt++) {
            const int T = nt * 8 + 2 * cl;
            const float* b0 = sred + wg * 1040 + rl * 65 + T;
            const float* b1 = sred + wg * 1040 + (rl + 8) * 65 + T;
            out[(size_t)T * NOUT + R0g]           = (d[nt][0] + b0[0]) * sc0 + bi0;
            out[(size_t)(T + 1) * NOUT + R0g]     = (d[nt][1] + b0[1]) * sc0 + bi0;
            out[(size_t)T * NOUT + R0g + 8]       = (d[nt][2] + b1[0]) * sc1 + bi1;
            out[(size_t)(T + 1) * NOUT + R0g + 8] = (d[nt][3] + b1[1]) * sc1 + bi1;
        }
    }
}

// ---------------------------------------------------------------------------
extern "C" void kernel_launch(void* const* d_in, const int* in_sizes, int n_in,
                              void* d_out, int out_size) {
    (void)in_sizes; (void)n_in; (void)out_size;
    const float* x    = (const float*)d_in[0];
    const int*   wpk  = (const int*)d_in[1];
    const float* wsc  = (const float*)d_in[2];
    const float* bias = (const float*)d_in[3];
    float* out = (float*)d_out;

    cudaFuncSetAttribute(qmain, cudaFuncAttributeMaxDynamicSharedMemorySize, SMEM_TOTAL);
    convert_x<<<512, 256>>>(x);                               // 131072 threads
    qmain<<<GRID_N, 512, SMEM_TOTAL>>>(wpk, wsc, bias, out);  // 112 CTAs, one wave
}

// round 16
// speedup vs baseline: 1.1100x; 1.1100x over previous
#include <cuda_runtime.h>
#include <cuda_fp16.h>
#include <cstdint>

// ---------------------------------------------------------------------------
// Problem constants
// ---------------------------------------------------------------------------
#define M_TOK   64
#define KDIM    8192
#define NOUT    14336
#define KW      (KDIM / 2)          // 4096 int32 per output row
#define NTILE   128
#define GRID_N  (NOUT / NTILE)      // 112 CTAs = one wave

// Dynamic SMEM: 4 warp-groups x 2-stage x ring (2 x 16KB) at grp*32768;
// mbarriers at 131072. Rings reused for split-K partials after the mainloop.
#define MBAR_OFF 131072
#define SMEM_TOTAL 131200

// x (fp16, k-permuted + bank-swizzled) staged per 64-k chunk: 128 chunks x 8KB
__device__ __align__(16) unsigned char g_ximg[(size_t)M_TOK * KDIM * 2];  // 1 MB

// ---------------------------------------------------------------------------
// Helpers
// ---------------------------------------------------------------------------
__device__ __forceinline__ uint2 lds64(uint32_t addr) {
    uint2 r;
    asm volatile("ld.shared.v2.u32 {%0,%1}, [%2];" : "=r"(r.x), "=r"(r.y) : "r"(addr));
    return r;
}
__device__ __forceinline__ void mma16816(float* d, uint32_t a0, uint32_t a1,
                                         uint32_t a2, uint32_t a3,
                                         uint32_t b0, uint32_t b1) {
    asm volatile(
        "mma.sync.aligned.m16n8k16.row.col.f32.f16.f16.f32 "
        "{%0,%1,%2,%3}, {%4,%5,%6,%7}, {%8,%9}, {%0,%1,%2,%3};"
        : "+f"(d[0]), "+f"(d[1]), "+f"(d[2]), "+f"(d[3])
        : "r"(a0), "r"(a1), "r"(a2), "r"(a3), "r"(b0), "r"(b1));
}

#define MBARRIER_INIT(addr, cnt) \
    asm volatile("mbarrier.init.shared.b64 [%0], %1;" :: "r"(addr), "r"(cnt) : "memory")
#define MBARRIER_EXPECT_TX(addr, bytes) \
    asm volatile("mbarrier.arrive.expect_tx.shared.b64 _, [%0], %1;" \
                 :: "r"(addr), "r"(bytes) : "memory")
#define FENCE_PROXY_ASYNC() \
    asm volatile("fence.proxy.async.shared::cta;" ::: "memory")
#define BULK_G2S(dst, src, bytes, mbar) \
    asm volatile("cp.async.bulk.shared::cluster.global.mbarrier::complete_tx::bytes " \
                 "[%0], [%1], %2, [%3];" \
                 :: "r"(dst), "l"(src), "r"(bytes), "r"(mbar) : "memory")
#define MBARRIER_WAIT_PARITY(addr, parity) do {                                          \
    uint32_t _m = (addr), _p = (parity), _done;                                          \
    asm volatile("{ .reg .pred p; mbarrier.try_wait.parity.acquire.cta.shared::cta.b64 " \
                 "p, [%1], %2; selp.b32 %0, 1, 0, p; }"                                  \
                 : "=r"(_done) : "r"(_m), "r"(_p) : "memory");                           \
    if (!_done) {                                                                        \
        asm volatile("{ .reg .pred P1; WL_%=: "                                          \
                     "mbarrier.try_wait.parity.acquire.cta.shared::cta.b64 P1, [%0], %1, 0x989680; " \
                     "@P1 bra.uni WD_%=; bra.uni WL_%=; WD_%=: }"                        \
                     :: "r"(_m), "r"(_p) : "memory");                                    \
    } } while (0)

// Per-warp-group barrier (128 threads): decouples the four k-split pipelines.
#define GROUP_BAR(grp_) \
    asm volatile("bar.sync %0, 128;" :: "r"((grp_) + 1) : "memory")

// int4-pair dequant: one int32 (value 0..255; lo nibble = even k) -> f16x2 {qlo,qhi}.
// lo half = 0x6408 ^ nibLo = 1032 + qlo (exact); HSUB2 by 1032 -> exact signed int4.
__device__ __forceinline__ uint32_t dq2(uint32_t v) {
    uint32_t t = (v & 0xFu) ^ 0x64086408u;
    uint32_t p = t ^ ((v << 12) & 0x000F0000u);
    __half2 hp = *reinterpret_cast<__half2*>(&p);
    __half2 r = __hsub2(hp, __half2half2(__ushort_as_half((unsigned short)0x6408)));
    return *reinterpret_cast<uint32_t*>(&r);
}

// ---------------------------------------------------------------------------
// Pre-kernel: x [64,8192] f32 -> f16 with the k-permutation + LDS swizzle baked in.
// Chunk cc covers physical k [cc*64, cc*64+64). Granule q (q = 4c+s, c=q>>2, s=q&3)
// stores 4 halves = physical k {8c+2s, 8c+2s+1, 32+8c+2s, 33+8c+2s} at byte offset
// tok*128 + ((q ^ (tok&7)) * 8) inside the 8KB chunk tile.
// ---------------------------------------------------------------------------
__global__ void convert_x(const float* __restrict__ x) {
    int tg  = blockIdx.x * 256 + threadIdx.x;    // 131072 threads
    int cc  = tg >> 10;
    int rem = tg & 1023;
    int tok = rem >> 4;
    int q   = rem & 15;
    int c = q >> 2, s = q & 3;
    int k0 = cc * 64 + 8 * c + 2 * s;
    float2 v0 = *reinterpret_cast<const float2*>(x + (size_t)tok * KDIM + k0);
    float2 v1 = *reinterpret_cast<const float2*>(x + (size_t)tok * KDIM + k0 + 32);
    __half2 h0 = __floats2half2_rn(v0.x, v0.y);
    __half2 h1 = __floats2half2_rn(v1.x, v1.y);
    uint2 st;
    st.x = *reinterpret_cast<uint32_t*>(&h0);
    st.y = *reinterpret_cast<uint32_t*>(&h1);
    *reinterpret_cast<uint2*>(g_ximg + (size_t)cc * 8192 + tok * 128 +
                              ((q ^ (tok & 7)) << 3)) = st;
}

// ---------------------------------------------------------------------------
// Main kernel: CTA = 128 out-rows x 64 tokens, 512 threads / 16 warps.
// 4-way SPLIT-K: group g (warps 4g..4g+3) owns k in [g*2048, (g+1)*2048).
// FAT-ROW warps: each warp = 32 rows x 64 tokens -> x-LDS amplification
// drops 8x -> 4x (b-fragments loaded once feed TWO 16-row mma tiles),
// halving the crossbar traffic that was 51% of R14's runtime. Weights:
// gmem -> single 32-reg buffer -> dq2 (components retire per s-step, so
// next-half LDGs pipeline behind compute). x staged by cp.async.bulk with
// per-group mbarriers; 4-way split-K reduction through the x rings.
// ---------------------------------------------------------------------------
__global__ __launch_bounds__(512, 1)
void qmain(const int* __restrict__ wp, const float* __restrict__ ws,
           const float* __restrict__ bias, float* __restrict__ out) {
    extern __shared__ __align__(16) unsigned char smem[];

    const int tid  = threadIdx.x;
    const int lane = tid & 31, warp = tid >> 5;       // warp 0..15
    const int grp  = warp >> 2;                       // 0..3: k-split group
    const int wr   = warp & 3;                        // row-warp within group
    const int rl = lane >> 2, cl = lane & 3;
    const int tl = tid & 127;                         // thread index within group
    const int r0 = blockIdx.x * NTILE;

    const uint32_t sb = (uint32_t)__cvta_generic_to_shared(smem);
    const uint32_t ringbase = (uint32_t)grp * 32768u;
    const uint32_t mb0 = sb + MBAR_OFF + (uint32_t)grp * 32u;
    const uint32_t mb1 = mb0 + 16u;

    // weight base: row (r0 + wr*32 + rl), group k-offset grp*1024 int32s,
    // this thread starts at int32 4*cl. rh (0..3) adds rh*8 rows = rh*8*KW.
    const int* wsrc = wp + (size_t)(r0 + wr * 32 + rl) * KW + grp * 1024 + 4 * cl;

    // x fragment bases: token = nt*8 + rl; granule offset gqb ^ (s<<3)
    uint32_t baddr[8];
#pragma unroll
    for (int nt = 0; nt < 8; nt++)
        baddr[nt] = sb + ringbase + (uint32_t)(nt * 8 + rl) * 128;
    const uint32_t gqb = ((uint32_t)((4 * cl) ^ rl)) << 3;

    // LOADW: local half-chunk h (0..31) -> W[4][2]; guarded for the tail
#define LOADW(W, h_) do {                                                       \
        if ((h_) < 32) {                                                        \
            _Pragma("unroll")                                                   \
            for (int rh_ = 0; rh_ < 4; rh_++) {                                 \
                const int* p_ = wsrc + rh_ * (8 * KW) + (h_) * 32;              \
                W[rh_][0] = *reinterpret_cast<const uint4*>(p_);                \
                W[rh_][1] = *reinterpret_cast<const uint4*>(p_ + 16);           \
            }                                                                   \
        } } while (0)

#define COMP4(u4, s_) ((s_) == 0 ? (u4).x : (s_) == 1 ? (u4).y : (s_) == 2 ? (u4).z : (u4).w)

#define COMPUTE(W, sx_) do {                                                    \
        _Pragma("unroll")                                                       \
        for (int s_ = 0; s_ < 4; s_++) {                                        \
            uint32_t a00 = dq2(COMP4(W[0][0], s_));                             \
            uint32_t a01 = dq2(COMP4(W[1][0], s_));                             \
            uint32_t a02 = dq2(COMP4(W[0][1], s_));                             \
            uint32_t a03 = dq2(COMP4(W[1][1], s_));                             \
            uint32_t a10 = dq2(COMP4(W[2][0], s_));                             \
            uint32_t a11 = dq2(COMP4(W[3][0], s_));                             \
            uint32_t a12 = dq2(COMP4(W[2][1], s_));                             \
            uint32_t a13 = dq2(COMP4(W[3][1], s_));                             \
            const uint32_t go_ = (sx_) + (gqb ^ ((uint32_t)s_ << 3));           \
            _Pragma("unroll")                                                   \
            for (int nt_ = 0; nt_ < 8; nt_++) {                                 \
                uint2 b_ = lds64(baddr[nt_] + go_);                             \
                mma16816(d0[nt_], a00, a01, a02, a03, b_.x, b_.y);              \
                mma16816(d1[nt_], a10, a11, a12, a13, b_.x, b_.y);              \
            }                                                                   \
        } } while (0)

    // x chunk j (0..15) of this group = g_ximg block (grp*16 + j)
#define ISSUE_BULK(j_, slot_) do {                                              \
        const unsigned char* xg_ = g_ximg + (size_t)(grp * 16 + (j_)) * 16384;  \
        const uint32_t xd_ = sb + ringbase + (uint32_t)(slot_) * 16384u;        \
        const uint32_t mb_ = (slot_) ? mb1 : mb0;                               \
        MBARRIER_EXPECT_TX(mb_, 16384u);                                        \
        BULK_G2S(xd_, xg_, 16384u, mb_);                                        \
    } while (0)

    uint4 W[4][2];
    float d0[8][4] = {}, d1[8][4] = {};

    if (tid == 0) {
#pragma unroll
        for (int g = 0; g < 8; g++)
            MBARRIER_INIT(sb + MBAR_OFF + (uint32_t)g * 16u, 1);
    }
    __syncthreads();
    if (tl == 0) {
        FENCE_PROXY_ASYNC();
        ISSUE_BULK(0, 0);
        ISSUE_BULK(1, 1);
    }

    LOADW(W, 0);

    for (int j = 0; j < 16; j++) {       // 16 chunks x 128 k per group
        MBARRIER_WAIT_PARITY((j & 1) ? mb1 : mb0, (uint32_t)((j >> 1) & 1));
        const uint32_t sx = (uint32_t)(j & 1) * 16384u;

        COMPUTE(W, sx);                  // half 2j
        LOADW(W, 2 * j + 1);
        COMPUTE(W, sx + 8192u);          // half 2j+1
        LOADW(W, 2 * j + 2);             // next chunk's 1st half (guarded)

        GROUP_BAR(grp);                  // this group done reading stage j&1
        if (tl == 0 && j + 2 < 16) ISSUE_BULK(j + 2, j & 1);
    }

    // ---- 4-way split-K reduction + epilogue (rings reused as partials) ----
    __syncthreads();                     // all groups fully done with rings

    float* sred = reinterpret_cast<float*>(smem);
    if (grp > 0) {
        float* buf = sred + (size_t)(grp - 1) * 8320;   // 128 rows x 65 floats
#pragma unroll
        for (int nt = 0; nt < 8; nt++) {
            const int T = nt * 8 + 2 * cl;
            float* p00 = buf + (wr * 32 + rl) * 65 + T;        // mt0, row rl
            float* p01 = p00 + 8 * 65;                         // mt0, row rl+8
            float* p10 = buf + (wr * 32 + 16 + rl) * 65 + T;   // mt1, row rl
            float* p11 = p10 + 8 * 65;
            p00[0] = d0[nt][0]; p00[1] = d0[nt][1];
            p01[0] = d0[nt][2]; p01[1] = d0[nt][3];
            p10[0] = d1[nt][0]; p10[1] = d1[nt][1];
            p11[0] = d1[nt][2]; p11[1] = d1[nt][3];
        }
    }
    __syncthreads();
    if (grp == 0) {
        const int Ra = r0 + wr * 32 + rl;        // mt0 rows: Ra, Ra+8
        const int Rb = Ra + 16;                  // mt1 rows: Rb, Rb+8
        const float sa0 = ws[Ra],      ba0 = bias[Ra];
        const float sa1 = ws[Ra + 8],  ba1 = bias[Ra + 8];
        const float sb0 = ws[Rb],      bb0 = bias[Rb];
        const float sb1 = ws[Rb + 8],  bb1 = bias[Rb + 8];
#pragma unroll
        for (int nt = 0; nt < 8; nt++) {
            const int T = nt * 8 + 2 * cl;
            const int ba_ = (wr * 32 + rl) * 65 + T;
            const int bb_ = (wr * 32 + 16 + rl) * 65 + T;
#pragma unroll
            for (int e = 0; e < 2; e++) {        // e: token T+e
                float v0 = d0[nt][e]     + sred[ba_ + e]          + sred[8320 + ba_ + e]          + sred[16640 + ba_ + e];
                float v1 = d0[nt][2 + e] + sred[ba_ + 520 + e]    + sred[8320 + ba_ + 520 + e]    + sred[16640 + ba_ + 520 + e];
                float v2 = d1[nt][e]     + sred[bb_ + e]          + sred[8320 + bb_ + e]          + sred[16640 + bb_ + e];
                float v3 = d1[nt][2 + e] + sred[bb_ + 520 + e]    + sred[8320 + bb_ + 520 + e]    + sred[16640 + bb_ + 520 + e];
                float* o = out + (size_t)(T + e) * NOUT;
                o[Ra]     = v0 * sa0 + ba0;
                o[Ra + 8] = v1 * sa1 + ba1;
                o[Rb]     = v2 * sb0 + bb0;
                o[Rb + 8] = v3 * sb1 + bb1;
            }
        }
    }
}

// ---------------------------------------------------------------------------
extern "C" void kernel_launch(void* const* d_in, const int* in_sizes, int n_in,
                              void* d_out, int out_size) {
    (void)in_sizes; (void)n_in; (void)out_size;
    const float* x    = (const float*)d_in[0];
    const int*   wpk  = (const int*)d_in[1];
    const float* wsc  = (const float*)d_in[2];
    const float* bias = (const float*)d_in[3];
    float* out = (float*)d_out;

    cudaFuncSetAttribute(qmain, cudaFuncAttributeMaxDynamicSharedMemorySize, SMEM_TOTAL);
    convert_x<<<512, 256>>>(x);                               // 131072 threads
    qmain<<<GRID_N, 512, SMEM_TOTAL>>>(wpk, wsc, bias, out);  // 112 CTAs, one wave
}

// round 17
// speedup vs baseline: 1.1428x; 1.0296x over previous
#include <cuda_runtime.h>
#include <cuda_fp16.h>
#include <cstdint>

// ---------------------------------------------------------------------------
// Problem constants
// ---------------------------------------------------------------------------
#define M_TOK   64
#define KDIM    8192
#define NOUT    14336
#define KW      (KDIM / 2)          // 4096 int32 per output row
#define NTILE   112                 // 14336 = 128 x 112 -> grid 128 of 148 SMs
#define GRID_N  (NOUT / NTILE)      // 128 CTAs = one wave, 86.5% chip fill

// Dynamic SMEM: 4 warp-groups x 2-stage x ring (2 x 16KB) at grp*32768;
// mbarriers at 131072. Rings reused for split-K partials after the mainloop.
#define MBAR_OFF 131072
#define SMEM_TOTAL 131200
#define SRF 7280                    // floats per reduction buffer (112 x 65)

// x (fp16, k-permuted + bank-swizzled) staged per 64-k chunk: 128 chunks x 8KB
__device__ __align__(16) unsigned char g_ximg[(size_t)M_TOK * KDIM * 2];  // 1 MB

// ---------------------------------------------------------------------------
// Helpers
// ---------------------------------------------------------------------------
__device__ __forceinline__ uint2 lds64(uint32_t addr) {
    uint2 r;
    asm volatile("ld.shared.v2.u32 {%0,%1}, [%2];" : "=r"(r.x), "=r"(r.y) : "r"(addr));
    return r;
}
__device__ __forceinline__ void mma16816(float* d, uint32_t a0, uint32_t a1,
                                         uint32_t a2, uint32_t a3,
                                         uint32_t b0, uint32_t b1) {
    asm volatile(
        "mma.sync.aligned.m16n8k16.row.col.f32.f16.f16.f32 "
        "{%0,%1,%2,%3}, {%4,%5,%6,%7}, {%8,%9}, {%0,%1,%2,%3};"
        : "+f"(d[0]), "+f"(d[1]), "+f"(d[2]), "+f"(d[3])
        : "r"(a0), "r"(a1), "r"(a2), "r"(a3), "r"(b0), "r"(b1));
}

#define MBARRIER_INIT(addr, cnt) \
    asm volatile("mbarrier.init.shared.b64 [%0], %1;" :: "r"(addr), "r"(cnt) : "memory")
#define MBARRIER_EXPECT_TX(addr, bytes) \
    asm volatile("mbarrier.arrive.expect_tx.shared.b64 _, [%0], %1;" \
                 :: "r"(addr), "r"(bytes) : "memory")
#define FENCE_PROXY_ASYNC() \
    asm volatile("fence.proxy.async.shared::cta;" ::: "memory")
#define BULK_G2S(dst, src, bytes, mbar) \
    asm volatile("cp.async.bulk.shared::cluster.global.mbarrier::complete_tx::bytes " \
                 "[%0], [%1], %2, [%3];" \
                 :: "r"(dst), "l"(src), "r"(bytes), "r"(mbar) : "memory")
#define MBARRIER_WAIT_PARITY(addr, parity) do {                                          \
    uint32_t _m = (addr), _p = (parity), _done;                                          \
    asm volatile("{ .reg .pred p; mbarrier.try_wait.parity.acquire.cta.shared::cta.b64 " \
                 "p, [%1], %2; selp.b32 %0, 1, 0, p; }"                                  \
                 : "=r"(_done) : "r"(_m), "r"(_p) : "memory");                           \
    if (!_done) {                                                                        \
        asm volatile("{ .reg .pred P1; WL_%=: "                                          \
                     "mbarrier.try_wait.parity.acquire.cta.shared::cta.b64 P1, [%0], %1, 0x989680; " \
                     "@P1 bra.uni WD_%=; bra.uni WL_%=; WD_%=: }"                        \
                     :: "r"(_m), "r"(_p) : "memory");                                    \
    } } while (0)

// Per-warp-group barrier (128 threads): decouples the four k-split pipelines.
#define GROUP_BAR(grp_) \
    asm volatile("bar.sync %0, 128;" :: "r"((grp_) + 1) : "memory")

// int4-pair dequant: one int32 (value 0..255; lo nibble = even k) -> f16x2 {qlo,qhi}.
// lo half = 0x6408 ^ nibLo = 1032 + qlo (exact); HSUB2 by 1032 -> exact signed int4.
__device__ __forceinline__ uint32_t dq2(uint32_t v) {
    uint32_t t = (v & 0xFu) ^ 0x64086408u;
    uint32_t p = t ^ ((v << 12) & 0x000F0000u);
    __half2 hp = *reinterpret_cast<__half2*>(&p);
    __half2 r = __hsub2(hp, __half2half2(__ushort_as_half((unsigned short)0x6408)));
    return *reinterpret_cast<uint32_t*>(&r);
}

// ---------------------------------------------------------------------------
// Pre-kernel: x [64,8192] f32 -> f16 with the k-permutation + LDS swizzle baked in.
// Chunk cc covers physical k [cc*64, cc*64+64). Granule q (q = 4c+s, c=q>>2, s=q&3)
// stores 4 halves = physical k {8c+2s, 8c+2s+1, 32+8c+2s, 33+8c+2s} at byte offset
// tok*128 + ((q ^ (tok&7)) * 8) inside the 8KB chunk tile.
// ---------------------------------------------------------------------------
__global__ void convert_x(const float* __restrict__ x) {
    int tg  = blockIdx.x * 256 + threadIdx.x;    // 131072 threads
    int cc  = tg >> 10;
    int rem = tg & 1023;
    int tok = rem >> 4;
    int q   = rem & 15;
    int c = q >> 2, s = q & 3;
    int k0 = cc * 64 + 8 * c + 2 * s;
    float2 v0 = *reinterpret_cast<const float2*>(x + (size_t)tok * KDIM + k0);
    float2 v1 = *reinterpret_cast<const float2*>(x + (size_t)tok * KDIM + k0 + 32);
    __half2 h0 = __floats2half2_rn(v0.x, v0.y);
    __half2 h1 = __floats2half2_rn(v1.x, v1.y);
    uint2 st;
    st.x = *reinterpret_cast<uint32_t*>(&h0);
    st.y = *reinterpret_cast<uint32_t*>(&h1);
    *reinterpret_cast<uint2*>(g_ximg + (size_t)cc * 8192 + tok * 128 +
                              ((q ^ (tok & 7)) << 3)) = st;
}

// ---------------------------------------------------------------------------
// Main kernel: CTA = 112 out-rows x 64 tokens, 512 threads / 16 warps, grid
// 128 (one wave, 86.5% chip fill vs 75.7% at 112 CTAs). 4-way SPLIT-K:
// group g = warps {g, g+4, g+8, g+12} owns k in [g*2048, (g+1)*2048).
// Row-warps: wr = warp>>2; wr 0..2 are FAT (32 rows), wr 3 is THIN (16 rows,
// rows 96..111, d0 only). grp = warp&3 so the four thin warps land on FOUR
// DIFFERENT SMSPs -> per-SMSP load = 3 fat + 1 thin = 0.875x of the 128-row
// kernel. Weights gmem->regs->dq2; x via cp.async.bulk rings per group.
// ---------------------------------------------------------------------------
__global__ __launch_bounds__(512, 1)
void qmain(const int* __restrict__ wp, const float* __restrict__ ws,
           const float* __restrict__ bias, float* __restrict__ out) {
    extern __shared__ __align__(16) unsigned char smem[];

    const int tid  = threadIdx.x;
    const int lane = tid & 31, warp = tid >> 5;       // warp 0..15
    const int grp  = warp & 3;                        // k-split group (SMSP-spread)
    const int wr   = warp >> 2;                       // row-warp 0..3
    const bool fat = (wr < 3);
    const int rl = lane >> 2, cl = lane & 3;
    const int r0 = blockIdx.x * NTILE;

    const uint32_t sb = (uint32_t)__cvta_generic_to_shared(smem);
    const uint32_t ringbase = (uint32_t)grp * 32768u;
    const uint32_t mb0 = sb + MBAR_OFF + (uint32_t)grp * 32u;
    const uint32_t mb1 = mb0 + 16u;

    // weight base: row (r0 + wr*32 + rl); rh adds rh*8 rows. Thin: rows 96..111.
    const int* wsrc = wp + (size_t)(r0 + wr * 32 + rl) * KW + grp * 1024 + 4 * cl;

    // x fragment bases: token = nt*8 + rl; granule offset gqb ^ (s<<3)
    uint32_t baddr[8];
#pragma unroll
    for (int nt = 0; nt < 8; nt++)
        baddr[nt] = sb + ringbase + (uint32_t)(nt * 8 + rl) * 128;
    const uint32_t gqb = ((uint32_t)((4 * cl) ^ rl)) << 3;

#define LOADW_FAT(W, h_) do {                                                   \
        if ((h_) < 32) {                                                        \
            _Pragma("unroll")                                                   \
            for (int rh_ = 0; rh_ < 4; rh_++) {                                 \
                const int* p_ = wsrc + rh_ * (8 * KW) + (h_) * 32;              \
                W[rh_][0] = *reinterpret_cast<const uint4*>(p_);                \
                W[rh_][1] = *reinterpret_cast<const uint4*>(p_ + 16);           \
            }                                                                   \
        } } while (0)

#define LOADW_THIN(W, h_) do {                                                  \
        if ((h_) < 32) {                                                        \
            _Pragma("unroll")                                                   \
            for (int rh_ = 0; rh_ < 2; rh_++) {                                 \
                const int* p_ = wsrc + rh_ * (8 * KW) + (h_) * 32;              \
                W[rh_][0] = *reinterpret_cast<const uint4*>(p_);                \
                W[rh_][1] = *reinterpret_cast<const uint4*>(p_ + 16);           \
            }                                                                   \
        } } while (0)

#define COMP4(u4, s_) ((s_) == 0 ? (u4).x : (s_) == 1 ? (u4).y : (s_) == 2 ? (u4).z : (u4).w)

#define COMPUTE_FAT(W, sx_) do {                                                \
        _Pragma("unroll")                                                       \
        for (int s_ = 0; s_ < 4; s_++) {                                        \
            uint32_t a00 = dq2(COMP4(W[0][0], s_));                             \
            uint32_t a01 = dq2(COMP4(W[1][0], s_));                             \
            uint32_t a02 = dq2(COMP4(W[0][1], s_));                             \
            uint32_t a03 = dq2(COMP4(W[1][1], s_));                             \
            uint32_t a10 = dq2(COMP4(W[2][0], s_));                             \
            uint32_t a11 = dq2(COMP4(W[3][0], s_));                             \
            uint32_t a12 = dq2(COMP4(W[2][1], s_));                             \
            uint32_t a13 = dq2(COMP4(W[3][1], s_));                             \
            const uint32_t go_ = (sx_) + (gqb ^ ((uint32_t)s_ << 3));           \
            _Pragma("unroll")                                                   \
            for (int nt_ = 0; nt_ < 8; nt_++) {                                 \
                uint2 b_ = lds64(baddr[nt_] + go_);                             \
                mma16816(d0[nt_], a00, a01, a02, a03, b_.x, b_.y);              \
                mma16816(d1[nt_], a10, a11, a12, a13, b_.x, b_.y);              \
            }                                                                   \
        } } while (0)

#define COMPUTE_THIN(W, sx_) do {                                               \
        _Pragma("unroll")                                                       \
        for (int s_ = 0; s_ < 4; s_++) {                                        \
            uint32_t a00 = dq2(COMP4(W[0][0], s_));                             \
            uint32_t a01 = dq2(COMP4(W[1][0], s_));                             \
            uint32_t a02 = dq2(COMP4(W[0][1], s_));                             \
            uint32_t a03 = dq2(COMP4(W[1][1], s_));                             \
            const uint32_t go_ = (sx_) + (gqb ^ ((uint32_t)s_ << 3));           \
            _Pragma("unroll")                                                   \
            for (int nt_ = 0; nt_ < 8; nt_++) {                                 \
                uint2 b_ = lds64(baddr[nt_] + go_);                             \
                mma16816(d0[nt_], a00, a01, a02, a03, b_.x, b_.y);              \
            }                                                                   \
        } } while (0)

    // x chunk j (0..15) of this group = g_ximg block (grp*16 + j)
#define ISSUE_BULK(j_, slot_) do {                                              \
        const unsigned char* xg_ = g_ximg + (size_t)(grp * 16 + (j_)) * 16384;  \
        const uint32_t xd_ = sb + ringbase + (uint32_t)(slot_) * 16384u;        \
        const uint32_t mb_ = (slot_) ? mb1 : mb0;                               \
        MBARRIER_EXPECT_TX(mb_, 16384u);                                        \
        BULK_G2S(xd_, xg_, 16384u, mb_);                                        \
    } while (0)

    uint4 W[4][2];
    float d0[8][4] = {}, d1[8][4] = {};

    if (tid == 0) {
#pragma unroll
        for (int g = 0; g < 8; g++)
            MBARRIER_INIT(sb + MBAR_OFF + (uint32_t)g * 16u, 1);
    }
    __syncthreads();
    if (wr == 0 && lane == 0) {          // warp g leads group g (grp = warp&3)
        FENCE_PROXY_ASYNC();
        ISSUE_BULK(0, 0);
        ISSUE_BULK(1, 1);
    }

    if (fat) {
        LOADW_FAT(W, 0);
        for (int j = 0; j < 16; j++) {
            MBARRIER_WAIT_PARITY((j & 1) ? mb1 : mb0, (uint32_t)((j >> 1) & 1));
            const uint32_t sx = (uint32_t)(j & 1) * 16384u;
            COMPUTE_FAT(W, sx);
            LOADW_FAT(W, 2 * j + 1);
            COMPUTE_FAT(W, sx + 8192u);
            LOADW_FAT(W, 2 * j + 2);
            GROUP_BAR(grp);
            if (wr == 0 && lane == 0 && j + 2 < 16) ISSUE_BULK(j + 2, j & 1);
        }
    } else {
        LOADW_THIN(W, 0);
        for (int j = 0; j < 16; j++) {
            MBARRIER_WAIT_PARITY((j & 1) ? mb1 : mb0, (uint32_t)((j >> 1) & 1));
            const uint32_t sx = (uint32_t)(j & 1) * 16384u;
            COMPUTE_THIN(W, sx);
            LOADW_THIN(W, 2 * j + 1);
            COMPUTE_THIN(W, sx + 8192u);
            LOADW_THIN(W, 2 * j + 2);
            GROUP_BAR(grp);
        }
    }

    // ---- 4-way split-K reduction + epilogue (rings reused as partials) ----
    __syncthreads();                     // all groups fully done with rings

    float* sred = reinterpret_cast<float*>(smem);
    if (grp > 0) {
        float* buf = sred + (size_t)(grp - 1) * SRF;   // 112 rows x 65 floats
        if (fat) {
#pragma unroll
            for (int nt = 0; nt < 8; nt++) {
                const int T = nt * 8 + 2 * cl;
                float* p00 = buf + (wr * 32 + rl) * 65 + T;        // mt0 row rl
                float* p01 = p00 + 520;                            // mt0 row rl+8
                float* p10 = buf + (wr * 32 + 16 + rl) * 65 + T;   // mt1 row rl
                float* p11 = p10 + 520;
                p00[0] = d0[nt][0]; p00[1] = d0[nt][1];
                p01[0] = d0[nt][2]; p01[1] = d0[nt][3];
                p10[0] = d1[nt][0]; p10[1] = d1[nt][1];
                p11[0] = d1[nt][2]; p11[1] = d1[nt][3];
            }
        } else {
#pragma unroll
            for (int nt = 0; nt < 8; nt++) {
                const int T = nt * 8 + 2 * cl;
                float* p00 = buf + (96 + rl) * 65 + T;
                float* p01 = p00 + 520;
                p00[0] = d0[nt][0]; p00[1] = d0[nt][1];
                p01[0] = d0[nt][2]; p01[1] = d0[nt][3];
            }
        }
    }
    __syncthreads();
    if (grp == 0) {
        if (fat) {
            const int Ra = r0 + wr * 32 + rl;        // rows Ra, Ra+8
            const int Rb = Ra + 16;                  // rows Rb, Rb+8
            const float sa0 = ws[Ra],      ba0 = bias[Ra];
            const float sa1 = ws[Ra + 8],  ba1 = bias[Ra + 8];
            const float sb0 = ws[Rb],      bb0 = bias[Rb];
            const float sb1 = ws[Rb + 8],  bb1 = bias[Rb + 8];
#pragma unroll
            for (int nt = 0; nt < 8; nt++) {
                const int T = nt * 8 + 2 * cl;
                const int ba_ = (wr * 32 + rl) * 65 + T;
                const int bb_ = (wr * 32 + 16 + rl) * 65 + T;
#pragma unroll
                for (int e = 0; e < 2; e++) {
                    float v0 = d0[nt][e]     + sred[ba_ + e]       + sred[SRF + ba_ + e]       + sred[2 * SRF + ba_ + e];
                    float v1 = d0[nt][2 + e] + sred[ba_ + 520 + e] + sred[SRF + ba_ + 520 + e] + sred[2 * SRF + ba_ + 520 + e];
                    float v2 = d1[nt][e]     + sred[bb_ + e]       + sred[SRF + bb_ + e]       + sred[2 * SRF + bb_ + e];
                    float v3 = d1[nt][2 + e] + sred[bb_ + 520 + e] + sred[SRF + bb_ + 520 + e] + sred[2 * SRF + bb_ + 520 + e];
                    float* o = out + (size_t)(T + e) * NOUT;
                    o[Ra]     = v0 * sa0 + ba0;
                    o[Ra + 8] = v1 * sa1 + ba1;
                    o[Rb]     = v2 * sb0 + bb0;
                    o[Rb + 8] = v3 * sb1 + bb1;
                }
            }
        } else {
            const int Ra = r0 + 96 + rl;             // rows Ra, Ra+8
            const float sa0 = ws[Ra],     ba0 = bias[Ra];
            const float sa1 = ws[Ra + 8], ba1 = bias[Ra + 8];
#pragma unroll
            for (int nt = 0; nt < 8; nt++) {
                const int T = nt * 8 + 2 * cl;
                const int ba_ = (96 + rl) * 65 + T;
#pragma unroll
                for (int e = 0; e < 2; e++) {
                    float v0 = d0[nt][e]     + sred[ba_ + e]       + sred[SRF + ba_ + e]       + sred[2 * SRF + ba_ + e];
                    float v1 = d0[nt][2 + e] + sred[ba_ + 520 + e] + sred[SRF + ba_ + 520 + e] + sred[2 * SRF + ba_ + 520 + e];
                    float* o = out + (size_t)(T + e) * NOUT;
                    o[Ra]     = v0 * sa0 + ba0;
                    o[Ra + 8] = v1 * sa1 + ba1;
                }
            }
        }
    }
}

// ---------------------------------------------------------------------------
extern "C" void kernel_launch(void* const* d_in, const int* in_sizes, int n_in,
                              void* d_out, int out_size) {
    (void)in_sizes; (void)n_in; (void)out_size;
    const float* x    = (const float*)d_in[0];
    const int*   wpk  = (const int*)d_in[1];
    const float* wsc  = (const float*)d_in[2];
    const float* bias = (const float*)d_in[3];
    float* out = (float*)d_out;

    cudaFuncSetAttribute(qmain, cudaFuncAttributeMaxDynamicSharedMemorySize, SMEM_TOTAL);
    convert_x<<<512, 256>>>(x);                               // 131072 threads
    qmain<<<GRID_N, 512, SMEM_TOTAL>>>(wpk, wsc, bias, out);  // 128 CTAs, one wave
}